// round 7
// baseline (speedup 1.0000x reference)
#include <cuda_runtime.h>
#include <cuda_bf16.h>
#include <cstdint>
#include <math.h>

#define BB 4
#define SS 4096
#define DD 256
#define D2 512

// ---- scratch (static __device__ globals; no allocation anywhere) ----
__device__ __nv_bfloat16 g_q[(size_t)BB * SS * DD];    // q bf16 (8 MB)
__device__ __nv_bfloat16 g_k[(size_t)BB * SS * DD];    // k bf16 (8 MB)
__device__ __nv_bfloat16 g_P[(size_t)BB * SS * SS];    // exp(logits) bf16 (134 MB)
__device__ float         g_z[BB * SS];                 // per-row sum-exp
__device__ float         g_w[BB * SS];                 // column weights

// ===========================================================================
// helpers
// ===========================================================================
__device__ __forceinline__ uint32_t smem_u32(const void* p) {
    uint32_t a;
    asm("{ .reg .u64 t; cvta.to.shared.u64 t, %1; cvt.u32.u64 %0, t; }" : "=r"(a) : "l"(p));
    return a;
}
__device__ __forceinline__ void ldmx4(uint32_t* r, uint32_t addr) {
    asm volatile("ldmatrix.sync.aligned.m8n8.x4.shared.b16 {%0,%1,%2,%3}, [%4];"
                 : "=r"(r[0]), "=r"(r[1]), "=r"(r[2]), "=r"(r[3]) : "r"(addr));
}
__device__ __forceinline__ void ldmx2(uint32_t* r, uint32_t addr) {
    asm volatile("ldmatrix.sync.aligned.m8n8.x2.shared.b16 {%0,%1}, [%2];"
                 : "=r"(r[0]), "=r"(r[1]) : "r"(addr));
}
__device__ __forceinline__ void mma16816(float* c, const uint32_t* a, const uint32_t* b) {
    asm volatile(
        "mma.sync.aligned.m16n8k16.row.col.f32.bf16.bf16.f32 "
        "{%0,%1,%2,%3}, {%4,%5,%6,%7}, {%8,%9}, {%0,%1,%2,%3};"
        : "+f"(c[0]), "+f"(c[1]), "+f"(c[2]), "+f"(c[3])
        : "r"(a[0]), "r"(a[1]), "r"(a[2]), "r"(a[3]), "r"(b[0]), "r"(b[1]));
}
__device__ __forceinline__ uint32_t pack_bf16(float x, float y) {
    return (uint32_t)__bfloat16_as_ushort(__float2bfloat16_rn(x))
         | ((uint32_t)__bfloat16_as_ushort(__float2bfloat16_rn(y)) << 16);
}
__device__ __forceinline__ void cp_async16(uint32_t dst, const void* src) {
    asm volatile("cp.async.cg.shared.global [%0], [%1], 16;" :: "r"(dst), "l"(src) : "memory");
}
// exact bf16 -> fp32 (bit shift)
__device__ __forceinline__ float bflo(uint32_t w) { return __uint_as_float(w << 16); }
__device__ __forceinline__ float bfhi(uint32_t w) { return __uint_as_float(w & 0xFFFF0000u); }

#define PADB 80           // bytes per smem tile row (64B data + 16B pad)
// logits stage: A 128 rows + B 256 rows, PADB stride
#define LG_A_B   10240
#define LG_B_B   20480
#define LG_STAGE (LG_A_B + LG_B_B)           // 30720
#define LG_SMEM  (4 * LG_STAGE)              // 122880

// ===========================================================================
// zero: clear accumulators each replay
// ===========================================================================
__global__ void zero_kernel(float* out, int n_out) {
    int i = blockIdx.x * blockDim.x + threadIdx.x;
    if (i < BB * SS) { g_w[i] = 0.0f; g_z[i] = 0.0f; }
    if (i < n_out)   out[i] = 0.0f;
}

// ===========================================================================
// projection: qk[B*S,512] = x @ W^T + bias, single bf16 HMMA (unchanged).
// ===========================================================================
__global__ __launch_bounds__(256, 2) void proj_kernel(
    const float* __restrict__ x, const float* __restrict__ W,
    const float* __restrict__ bias)
{
    __shared__ __align__(16) char tiles[2 * 128 * PADB];

    const int tid = threadIdx.x;
    const int lane = tid & 31, wid = tid >> 5;
    const int wm = wid >> 2, wn = wid & 3;

    const float* Ab = x + (size_t)blockIdx.y * 128 * DD;
    const float* Bb = W + (size_t)blockIdx.x * 128 * DD;
    const uint32_t sb = smem_u32(tiles);

    float acc[4][4][4];
#pragma unroll
    for (int m = 0; m < 4; m++)
#pragma unroll
        for (int n = 0; n < 4; n++)
#pragma unroll
            for (int u = 0; u < 4; u++) acc[m][n][u] = 0.0f;

    const uint32_t a_row = (uint32_t)(lane & 15);
    const uint32_t a_koff = (uint32_t)((lane >> 4) << 4);
    const uint32_t b_row = (uint32_t)(lane & 7);
    const uint32_t b_koff = (uint32_t)(((lane >> 3) & 1) << 4);

    for (int kt = 0; kt < 8; kt++) {
        __syncthreads();
#pragma unroll
        for (int i = 0; i < 8; i++) {
            int chunk = tid + i * 256;
            int arr = chunk >> 10;
            int c = chunk & 1023;
            int row = c >> 3, c4 = c & 7;
            const float* src = (arr ? Bb : Ab) + (size_t)row * DD + kt * 32 + c4 * 4;
            float4 v = *reinterpret_cast<const float4*>(src);
            uint2 p;
            p.x = pack_bf16(v.x, v.y);
            p.y = pack_bf16(v.z, v.w);
            *reinterpret_cast<uint2*>(tiles + arr * 10240 + row * PADB + c4 * 8) = p;
        }
        __syncthreads();

#pragma unroll
        for (int k16 = 0; k16 < 2; k16++) {
            const uint32_t kb = (uint32_t)(k16 * 32);
            uint32_t bh[4][2];
#pragma unroll
            for (int n = 0; n < 4; n++) {
                uint32_t boff = (uint32_t)(wn * 32 + n * 8 + b_row) * PADB + kb + b_koff;
                ldmx2(bh[n], sb + 10240 + boff);
            }
#pragma unroll
            for (int m = 0; m < 4; m++) {
                uint32_t aoff = (uint32_t)(wm * 64 + m * 16 + a_row) * PADB + kb + a_koff;
                uint32_t ah[4];
                ldmx4(ah, sb + aoff);
#pragma unroll
                for (int n = 0; n < 4; n++)
                    mma16816(acc[m][n], ah, bh[n]);
            }
        }
    }

    const int g = lane >> 2, t2 = (lane & 3) * 2;
#pragma unroll
    for (int m = 0; m < 4; m++) {
        const size_t grow = (size_t)blockIdx.y * 128 + wm * 64 + m * 16 + g;
#pragma unroll
        for (int n = 0; n < 4; n++) {
            const int col = blockIdx.x * 128 + wn * 32 + n * 8 + t2;
            const float b0 = bias[col], b1 = bias[col + 1];
            uint32_t p01 = pack_bf16(acc[m][n][0] + b0, acc[m][n][1] + b1);
            uint32_t p23 = pack_bf16(acc[m][n][2] + b0, acc[m][n][3] + b1);
            __nv_bfloat16* base = (col < DD) ? (g_q + col) : (g_k + (col - DD));
            *reinterpret_cast<uint32_t*>(base + grow * DD)       = p01;
            *reinterpret_cast<uint32_t*>(base + (grow + 8) * DD) = p23;
        }
    }
}

// ===========================================================================
// logits kernel: CTA = 128(q) x 256(k), K=256, single bf16 HMMA.
// 8 warps 2(m) x 4(n), warp tile 64x64 (acc 128 regs). 4-stage cp.async,
// 3-deep prefetch, ONE barrier per k-tile. Epilogue in 2 x 32KB halves.
// ===========================================================================
__global__ __launch_bounds__(256, 1) void logits_kernel() {
    extern __shared__ __align__(16) char tiles[];
    __shared__ float zrow[128];

    const int tid = threadIdx.x;
    const int lane = tid & 31, wid = tid >> 5;
    const int wm = wid >> 2, wn = wid & 3;
    const int nt = blockIdx.x, qt = blockIdx.y, b = blockIdx.z;

    if (tid < 128) zrow[tid] = 0.0f;

    const uint32_t sb = smem_u32(tiles);
    const __nv_bfloat16* Qs = g_q + ((size_t)b * SS + (size_t)qt * 128) * DD;
    const __nv_bfloat16* Ks = g_k + ((size_t)b * SS + (size_t)nt * 256) * DD;

    float acc[4][8][4];
#pragma unroll
    for (int m = 0; m < 4; m++)
#pragma unroll
        for (int n = 0; n < 8; n++)
#pragma unroll
            for (int u = 0; u < 4; u++) acc[m][n][u] = 0.0f;

    const uint32_t a_row = (uint32_t)(lane & 15);
    const uint32_t a_koff = (uint32_t)((lane >> 4) << 4);
    const uint32_t b_row = (uint32_t)(lane & 7);
    const uint32_t b_koff = (uint32_t)(((lane >> 3) & 1) << 4);

    // stage loader: A 512 chunks + B 1024 chunks of 16B = 6 per thread
#define LOAD_STAGE(kt, s)                                                        \
    do {                                                                         \
        _Pragma("unroll")                                                        \
        for (int i = 0; i < 6; i++) {                                            \
            int chunk = tid + i * 256;                                           \
            int isB = (chunk >= 512);                                            \
            int c = isB ? (chunk - 512) : chunk;                                 \
            int row = c >> 2, c4 = c & 3;                                        \
            const __nv_bfloat16* src = (isB ? Ks : Qs) + (size_t)row * DD + (kt) * 32 + c4 * 8; \
            cp_async16(sb + (uint32_t)(s) * LG_STAGE + (isB ? LG_A_B : 0) + row * PADB + c4 * 16, src); \
        }                                                                        \
        asm volatile("cp.async.commit_group;" ::: "memory");                     \
    } while (0)

    LOAD_STAGE(0, 0);
    LOAD_STAGE(1, 1);
    LOAD_STAGE(2, 2);

    for (int kt = 0; kt < 8; kt++) {
        if (kt <= 5)      asm volatile("cp.async.wait_group 2;" ::: "memory");
        else if (kt == 6) asm volatile("cp.async.wait_group 1;" ::: "memory");
        else              asm volatile("cp.async.wait_group 0;" ::: "memory");
        __syncthreads();
        if (kt + 3 < 8) LOAD_STAGE(kt + 3, (kt + 3) & 3);

        const uint32_t st = sb + (uint32_t)(kt & 3) * LG_STAGE;
#pragma unroll
        for (int k16 = 0; k16 < 2; k16++) {
            const uint32_t kb = (uint32_t)(k16 * 32);
            uint32_t bh[8][2];
#pragma unroll
            for (int n = 0; n < 8; n++) {
                uint32_t boff = (uint32_t)(wn * 64 + n * 8 + b_row) * PADB + kb + b_koff;
                ldmx2(bh[n], st + LG_A_B + boff);
            }
#pragma unroll
            for (int m = 0; m < 4; m++) {
                uint32_t aoff = (uint32_t)(wm * 64 + m * 16 + a_row) * PADB + kb + a_koff;
                uint32_t ah[4];
                ldmx4(ah, st + aoff);
#pragma unroll
                for (int n = 0; n < 8; n++)
                    mma16816(acc[m][n], ah, bh[n]);
            }
        }
    }
    __syncthreads();   // mainloop reads done; smem becomes P staging

    // ---- epilogue: two 128x128 halves (warps wn 0,1 -> half 0; 2,3 -> half 1)
    const int g = lane >> 2, t2 = (lane & 3) * 2;
    const size_t grow0 = (size_t)b * SS + (size_t)qt * 128;
#pragma unroll
    for (int r = 0; r < 2; r++) {
        if ((wn >> 1) == r) {
#pragma unroll
            for (int m = 0; m < 4; m++) {
                const int row_lo = wm * 64 + m * 16 + g;
                float zlo = 0.0f, zhi = 0.0f;
#pragma unroll
                for (int n = 0; n < 8; n++) {
                    float e0 = __expf(acc[m][n][0] * 0.0625f);
                    float e1 = __expf(acc[m][n][1] * 0.0625f);
                    float e2 = __expf(acc[m][n][2] * 0.0625f);
                    float e3 = __expf(acc[m][n][3] * 0.0625f);
                    zlo += e0 + e1;
                    zhi += e2 + e3;
                    const int lcol = (wn & 1) * 64 + n * 8 + t2;
                    *reinterpret_cast<uint32_t*>(tiles + row_lo * 256 + lcol * 2)       = pack_bf16(e0, e1);
                    *reinterpret_cast<uint32_t*>(tiles + (row_lo + 8) * 256 + lcol * 2) = pack_bf16(e2, e3);
                }
                atomicAdd(&zrow[row_lo], zlo);
                atomicAdd(&zrow[row_lo + 8], zhi);
            }
        }
        __syncthreads();
        // coalesced 16B stores of this 32KB half
#pragma unroll
        for (int i = 0; i < 8; i++) {
            int chunk = tid + i * 256;
            int row = chunk >> 4, c16 = chunk & 15;
            uint4 v = *reinterpret_cast<const uint4*>(tiles + row * 256 + c16 * 16);
            *reinterpret_cast<uint4*>(g_P + (grow0 + row) * SS + nt * 256 + r * 128 + c16 * 8) = v;
        }
        __syncthreads();
    }
    if (tid < 128)
        atomicAdd(&g_z[grow0 + tid], zrow[tid]);
}

// ===========================================================================
// column weights: w_k += sum_q P[q,k] / z_q.  Column-partitioned (unchanged).
// ===========================================================================
__global__ __launch_bounds__(256) void col_weights_kernel() {
    __shared__ float izs[512];
    __shared__ float ws[16][128];

    const int tid = threadIdx.x;
    const int r0 = blockIdx.x * 512;
    const int c0 = blockIdx.y * 128;
    const int b  = blockIdx.z;

    for (int i = tid; i < 512; i += 256)
        izs[i] = 1.0f / g_z[(size_t)b * SS + r0 + i];
    __syncthreads();

    const int c8 = tid & 15;
    const int rstripe = tid >> 4;

    float acc[8];
#pragma unroll
    for (int j = 0; j < 8; j++) acc[j] = 0.0f;

    const __nv_bfloat16* Pb = g_P + ((size_t)b * SS + r0 + rstripe) * SS + c0 + c8 * 8;
#pragma unroll 4
    for (int i = 0; i < 32; i++) {
        const float iz = izs[rstripe + i * 16];
        uint4 v = *reinterpret_cast<const uint4*>(Pb + (size_t)i * 16 * SS);
        const uint32_t w[4] = {v.x, v.y, v.z, v.w};
#pragma unroll
        for (int h = 0; h < 4; h++) {
            acc[2 * h]     = fmaf(bflo(w[h]), iz, acc[2 * h]);
            acc[2 * h + 1] = fmaf(bfhi(w[h]), iz, acc[2 * h + 1]);
        }
    }

#pragma unroll
    for (int j = 0; j < 8; j++) ws[rstripe][c8 * 8 + j] = acc[j];
    __syncthreads();

    if (tid < 128) {
        float s = 0.0f;
#pragma unroll
        for (int j = 0; j < 16; j++) s += ws[j][tid];
        atomicAdd(&g_w[(size_t)b * SS + c0 + tid], s);
    }
}

// ===========================================================================
// weighted pool: out[b,d] = sum_k w[b,k] * x[b,k,d]
// ===========================================================================
__global__ void out_kernel(const float* __restrict__ x, float* __restrict__ out) {
    const int b = blockIdx.y;
    const int k0 = blockIdx.x * 64;
    const int d = threadIdx.x;

    const float* xp = x + ((size_t)b * SS + k0) * DD + d;
    const float* wp = g_w + (size_t)b * SS + k0;
    float acc = 0.0f;
#pragma unroll 8
    for (int kk = 0; kk < 64; kk++)
        acc = fmaf(wp[kk], xp[(size_t)kk * DD], acc);
    atomicAdd(&out[b * DD + d], acc);
}

// ===========================================================================
extern "C" void kernel_launch(void* const* d_in, const int* in_sizes, int n_in,
                              void* d_out, int out_size) {
    const float* x    = (const float*)d_in[0];
    const float* W    = (const float*)d_in[1];
    const float* bias = (const float*)d_in[2];
    float* out = (float*)d_out;

    cudaFuncSetAttribute(logits_kernel, cudaFuncAttributeMaxDynamicSharedMemorySize, LG_SMEM);

    // 0) zero accumulators
    zero_kernel<<<64, 256>>>(out, out_size);

    // 1) projection (single bf16 HMMA), bf16 q/k out
    {
        dim3 grid(D2 / 128, (BB * SS) / 128);
        proj_kernel<<<grid, 256>>>(x, W, bias);
    }

    // 2) logits + exp + z  (bf16 HMMA 64x64 warp tiles, 4-stage cp.async)
    {
        dim3 grid(SS / 256, SS / 128, BB);
        logits_kernel<<<grid, 256, LG_SMEM>>>();
    }

    // 3) column weights
    {
        dim3 grid(SS / 512, SS / 128, BB);
        col_weights_kernel<<<grid, 256>>>();
    }

    // 4) weighted pool
    out_kernel<<<dim3(64, BB), 256>>>(x, out);
}

// round 8
// speedup vs baseline: 1.2642x; 1.2642x over previous
#include <cuda_runtime.h>
#include <cuda_bf16.h>
#include <cstdint>
#include <math.h>

#define BB 4
#define SS 4096
#define DD 256
#define D2 512

// ---- scratch (static __device__ globals; no allocation anywhere) ----
__device__ __nv_bfloat16 g_q[(size_t)BB * SS * DD];    // q bf16 (8 MB)
__device__ __nv_bfloat16 g_k[(size_t)BB * SS * DD];    // k bf16 (8 MB)
__device__ __nv_bfloat16 g_P[(size_t)BB * SS * SS];    // exp(logits) bf16 (134 MB)
__device__ float         g_z[BB * SS];                 // per-row sum-exp
__device__ float         g_w[BB * SS];                 // column weights

// ===========================================================================
// helpers
// ===========================================================================
__device__ __forceinline__ uint32_t smem_u32(const void* p) {
    uint32_t a;
    asm("{ .reg .u64 t; cvta.to.shared.u64 t, %1; cvt.u32.u64 %0, t; }" : "=r"(a) : "l"(p));
    return a;
}
__device__ __forceinline__ void ldmx4(uint32_t* r, uint32_t addr) {
    asm volatile("ldmatrix.sync.aligned.m8n8.x4.shared.b16 {%0,%1,%2,%3}, [%4];"
                 : "=r"(r[0]), "=r"(r[1]), "=r"(r[2]), "=r"(r[3]) : "r"(addr));
}
__device__ __forceinline__ void ldmx2(uint32_t* r, uint32_t addr) {
    asm volatile("ldmatrix.sync.aligned.m8n8.x2.shared.b16 {%0,%1}, [%2];"
                 : "=r"(r[0]), "=r"(r[1]) : "r"(addr));
}
__device__ __forceinline__ void mma16816(float* c, const uint32_t* a, const uint32_t* b) {
    asm volatile(
        "mma.sync.aligned.m16n8k16.row.col.f32.bf16.bf16.f32 "
        "{%0,%1,%2,%3}, {%4,%5,%6,%7}, {%8,%9}, {%0,%1,%2,%3};"
        : "+f"(c[0]), "+f"(c[1]), "+f"(c[2]), "+f"(c[3])
        : "r"(a[0]), "r"(a[1]), "r"(a[2]), "r"(a[3]), "r"(b[0]), "r"(b[1]));
}
__device__ __forceinline__ uint32_t pack_bf16(float x, float y) {
    return (uint32_t)__bfloat16_as_ushort(__float2bfloat16_rn(x))
         | ((uint32_t)__bfloat16_as_ushort(__float2bfloat16_rn(y)) << 16);
}
__device__ __forceinline__ void cp_async16(uint32_t dst, const void* src) {
    asm volatile("cp.async.cg.shared.global [%0], [%1], 16;" :: "r"(dst), "l"(src) : "memory");
}
// exact bf16 -> fp32 (bit shift)
__device__ __forceinline__ float bflo(uint32_t w) { return __uint_as_float(w << 16); }
__device__ __forceinline__ float bfhi(uint32_t w) { return __uint_as_float(w & 0xFFFF0000u); }

#define PADB 80        // bytes per smem tile row (64B data + 16B pad, conflict-free)
#define STAGE_B 20480  // one pipeline stage: A(128) + B(128) rows x PADB
#define LG_SMEM (3 * STAGE_B)

// ===========================================================================
// zero: clear accumulators each replay
// ===========================================================================
__global__ void zero_kernel(float* out, int n_out) {
    int i = blockIdx.x * blockDim.x + threadIdx.x;
    if (i < BB * SS) { g_w[i] = 0.0f; g_z[i] = 0.0f; }
    if (i < n_out)   out[i] = 0.0f;
}

// ===========================================================================
// projection: qk[B*S,512] = x @ W^T + bias, single bf16 HMMA (round-6, passing)
// ===========================================================================
__global__ __launch_bounds__(256, 2) void proj_kernel(
    const float* __restrict__ x, const float* __restrict__ W,
    const float* __restrict__ bias)
{
    __shared__ __align__(16) char tiles[2 * 128 * PADB];

    const int tid = threadIdx.x;
    const int lane = tid & 31, wid = tid >> 5;
    const int wm = wid >> 2, wn = wid & 3;

    const float* Ab = x + (size_t)blockIdx.y * 128 * DD;
    const float* Bb = W + (size_t)blockIdx.x * 128 * DD;
    const uint32_t sb = smem_u32(tiles);

    float acc[4][4][4];
#pragma unroll
    for (int m = 0; m < 4; m++)
#pragma unroll
        for (int n = 0; n < 4; n++)
#pragma unroll
            for (int u = 0; u < 4; u++) acc[m][n][u] = 0.0f;

    const uint32_t a_row = (uint32_t)(lane & 15);
    const uint32_t a_koff = (uint32_t)((lane >> 4) << 4);
    const uint32_t b_row = (uint32_t)(lane & 7);
    const uint32_t b_koff = (uint32_t)(((lane >> 3) & 1) << 4);

    for (int kt = 0; kt < 8; kt++) {
        __syncthreads();
#pragma unroll
        for (int i = 0; i < 8; i++) {
            int chunk = tid + i * 256;
            int arr = chunk >> 10;
            int c = chunk & 1023;
            int row = c >> 3, c4 = c & 7;
            const float* src = (arr ? Bb : Ab) + (size_t)row * DD + kt * 32 + c4 * 4;
            float4 v = *reinterpret_cast<const float4*>(src);
            uint2 p;
            p.x = pack_bf16(v.x, v.y);
            p.y = pack_bf16(v.z, v.w);
            *reinterpret_cast<uint2*>(tiles + arr * 10240 + row * PADB + c4 * 8) = p;
        }
        __syncthreads();

#pragma unroll
        for (int k16 = 0; k16 < 2; k16++) {
            const uint32_t kb = (uint32_t)(k16 * 32);
            uint32_t bh[4][2];
#pragma unroll
            for (int n = 0; n < 4; n++) {
                uint32_t boff = (uint32_t)(wn * 32 + n * 8 + b_row) * PADB + kb + b_koff;
                ldmx2(bh[n], sb + 10240 + boff);
            }
#pragma unroll
            for (int m = 0; m < 4; m++) {
                uint32_t aoff = (uint32_t)(wm * 64 + m * 16 + a_row) * PADB + kb + a_koff;
                uint32_t ah[4];
                ldmx4(ah, sb + aoff);
#pragma unroll
                for (int n = 0; n < 4; n++)
                    mma16816(acc[m][n], ah, bh[n]);
            }
        }
    }

    const int g = lane >> 2, t2 = (lane & 3) * 2;
#pragma unroll
    for (int m = 0; m < 4; m++) {
        const size_t grow = (size_t)blockIdx.y * 128 + wm * 64 + m * 16 + g;
#pragma unroll
        for (int n = 0; n < 4; n++) {
            const int col = blockIdx.x * 128 + wn * 32 + n * 8 + t2;
            const float b0 = bias[col], b1 = bias[col + 1];
            uint32_t p01 = pack_bf16(acc[m][n][0] + b0, acc[m][n][1] + b1);
            uint32_t p23 = pack_bf16(acc[m][n][2] + b0, acc[m][n][3] + b1);
            __nv_bfloat16* base = (col < DD) ? (g_q + col) : (g_k + (col - DD));
            *reinterpret_cast<uint32_t*>(base + grow * DD)       = p01;
            *reinterpret_cast<uint32_t*>(base + (grow + 8) * DD) = p23;
        }
    }
}

// ===========================================================================
// logits kernel: CTA = 128(q) x 128(k), K=256, single bf16 HMMA.
// 128 threads / 4 warps (2m x 2n), warp tile 64x64 -> ld:mma = 12:32.
// 3-stage cp.async (60 KB) -> 2 CTAs/SM for epilogue/mainloop overlap.
// Epilogue: P=exp(l/16) bf16 staged (32 KB) -> 16B-coalesced store; z sums.
// ===========================================================================
__global__ __launch_bounds__(128, 2) void logits_kernel() {
    extern __shared__ __align__(16) char tiles[];
    __shared__ float zrow[128];

    const int tid = threadIdx.x;
    const int lane = tid & 31, wid = tid >> 5;
    const int wm = wid >> 1, wn = wid & 1;
    const int nt = blockIdx.x, qt = blockIdx.y, b = blockIdx.z;

    zrow[tid] = 0.0f;

    const uint32_t sb = smem_u32(tiles);
    const __nv_bfloat16* Qs = g_q + ((size_t)b * SS + (size_t)qt * 128) * DD;
    const __nv_bfloat16* Ks = g_k + ((size_t)b * SS + (size_t)nt * 128) * DD;

    float acc[4][8][4];
#pragma unroll
    for (int m = 0; m < 4; m++)
#pragma unroll
        for (int n = 0; n < 8; n++)
#pragma unroll
            for (int u = 0; u < 4; u++) acc[m][n][u] = 0.0f;

    const uint32_t a_row = (uint32_t)(lane & 15);
    const uint32_t a_koff = (uint32_t)((lane >> 4) << 4);
    const uint32_t b_row = (uint32_t)(lane & 7);
    const uint32_t b_koff = (uint32_t)(((lane >> 3) & 1) << 4);

    // stage loader: 1024 x 16B chunks (A 512 | B 512), 8 per thread
#define LOAD_STAGE(kt, s)                                                        \
    do {                                                                         \
        _Pragma("unroll")                                                        \
        for (int i = 0; i < 8; i++) {                                            \
            int chunk = tid + i * 128;                                           \
            int arr = chunk >> 9;                                                \
            int c = chunk & 511;                                                 \
            int row = c >> 2, c4 = c & 3;                                        \
            const __nv_bfloat16* src = (arr ? Ks : Qs) + (size_t)row * DD + (kt) * 32 + c4 * 8; \
            cp_async16(sb + (uint32_t)(s) * STAGE_B + arr * 10240 + row * PADB + c4 * 16, src); \
        }                                                                        \
        asm volatile("cp.async.commit_group;" ::: "memory");                     \
    } while (0)

    LOAD_STAGE(0, 0);
    LOAD_STAGE(1, 1);

    int stage = 0;
    for (int kt = 0; kt < 8; kt++) {
        if (kt < 7) asm volatile("cp.async.wait_group 1;" ::: "memory");
        else        asm volatile("cp.async.wait_group 0;" ::: "memory");
        __syncthreads();
        if (kt + 2 < 8) {
            int ns = stage + 2; if (ns >= 3) ns -= 3;
            LOAD_STAGE(kt + 2, ns);
        }

        const uint32_t st = sb + (uint32_t)stage * STAGE_B;
#pragma unroll
        for (int k16 = 0; k16 < 2; k16++) {
            const uint32_t kb = (uint32_t)(k16 * 32);
            uint32_t bh[8][2];
#pragma unroll
            for (int n = 0; n < 8; n++) {
                uint32_t boff = (uint32_t)(wn * 64 + n * 8 + b_row) * PADB + kb + b_koff;
                ldmx2(bh[n], st + 10240 + boff);
            }
#pragma unroll
            for (int m = 0; m < 4; m++) {
                uint32_t aoff = (uint32_t)(wm * 64 + m * 16 + a_row) * PADB + kb + a_koff;
                uint32_t ah[4];
                ldmx4(ah, st + aoff);
#pragma unroll
                for (int n = 0; n < 8; n++)
                    mma16816(acc[m][n], ah, bh[n]);
            }
        }
        if (++stage == 3) stage = 0;
    }
    __syncthreads();   // mainloop reads done; smem becomes P staging (32 KB)

    // ---- epilogue: exp, pack to smem (128 x 128 bf16), z row sums ----
    const int g = lane >> 2, t2 = (lane & 3) * 2;
#pragma unroll
    for (int m = 0; m < 4; m++) {
        const int row_lo = wm * 64 + m * 16 + g;
        float zlo = 0.0f, zhi = 0.0f;
#pragma unroll
        for (int n = 0; n < 8; n++) {
            float e0 = __expf(acc[m][n][0] * 0.0625f);
            float e1 = __expf(acc[m][n][1] * 0.0625f);
            float e2 = __expf(acc[m][n][2] * 0.0625f);
            float e3 = __expf(acc[m][n][3] * 0.0625f);
            zlo += e0 + e1;
            zhi += e2 + e3;
            const int col = wn * 64 + n * 8 + t2;
            *reinterpret_cast<uint32_t*>(tiles + row_lo * 256 + col * 2)       = pack_bf16(e0, e1);
            *reinterpret_cast<uint32_t*>(tiles + (row_lo + 8) * 256 + col * 2) = pack_bf16(e2, e3);
        }
        atomicAdd(&zrow[row_lo], zlo);
        atomicAdd(&zrow[row_lo + 8], zhi);
    }
    __syncthreads();

    // ---- coalesced 16B stores: 2048 chunks / 128 threads = 16 each ----
    const size_t grow0 = (size_t)b * SS + (size_t)qt * 128;
#pragma unroll
    for (int i = 0; i < 16; i++) {
        int chunk = tid + i * 128;
        int row = chunk >> 4, c16 = chunk & 15;
        uint4 v = *reinterpret_cast<const uint4*>(tiles + row * 256 + c16 * 16);
        *reinterpret_cast<uint4*>(g_P + (grow0 + row) * SS + nt * 128 + c16 * 8) = v;
    }
    atomicAdd(&g_z[grow0 + tid], zrow[tid]);
}

// ===========================================================================
// column weights: w_k += sum_q P[q,k] / z_q.  Column-partitioned (unchanged).
// ===========================================================================
__global__ __launch_bounds__(256) void col_weights_kernel() {
    __shared__ float izs[512];
    __shared__ float ws[16][128];

    const int tid = threadIdx.x;
    const int r0 = blockIdx.x * 512;
    const int c0 = blockIdx.y * 128;
    const int b  = blockIdx.z;

    for (int i = tid; i < 512; i += 256)
        izs[i] = 1.0f / g_z[(size_t)b * SS + r0 + i];
    __syncthreads();

    const int c8 = tid & 15;
    const int rstripe = tid >> 4;

    float acc[8];
#pragma unroll
    for (int j = 0; j < 8; j++) acc[j] = 0.0f;

    const __nv_bfloat16* Pb = g_P + ((size_t)b * SS + r0 + rstripe) * SS + c0 + c8 * 8;
#pragma unroll 4
    for (int i = 0; i < 32; i++) {
        const float iz = izs[rstripe + i * 16];
        uint4 v = *reinterpret_cast<const uint4*>(Pb + (size_t)i * 16 * SS);
        const uint32_t w[4] = {v.x, v.y, v.z, v.w};
#pragma unroll
        for (int h = 0; h < 4; h++) {
            acc[2 * h]     = fmaf(bflo(w[h]), iz, acc[2 * h]);
            acc[2 * h + 1] = fmaf(bfhi(w[h]), iz, acc[2 * h + 1]);
        }
    }

#pragma unroll
    for (int j = 0; j < 8; j++) ws[rstripe][c8 * 8 + j] = acc[j];
    __syncthreads();

    if (tid < 128) {
        float s = 0.0f;
#pragma unroll
        for (int j = 0; j < 16; j++) s += ws[j][tid];
        atomicAdd(&g_w[(size_t)b * SS + c0 + tid], s);
    }
}

// ===========================================================================
// weighted pool: out[b,d] = sum_k w[b,k] * x[b,k,d]
// ===========================================================================
__global__ void out_kernel(const float* __restrict__ x, float* __restrict__ out) {
    const int b = blockIdx.y;
    const int k0 = blockIdx.x * 64;
    const int d = threadIdx.x;

    const float* xp = x + ((size_t)b * SS + k0) * DD + d;
    const float* wp = g_w + (size_t)b * SS + k0;
    float acc = 0.0f;
#pragma unroll 8
    for (int kk = 0; kk < 64; kk++)
        acc = fmaf(wp[kk], xp[(size_t)kk * DD], acc);
    atomicAdd(&out[b * DD + d], acc);
}

// ===========================================================================
extern "C" void kernel_launch(void* const* d_in, const int* in_sizes, int n_in,
                              void* d_out, int out_size) {
    const float* x    = (const float*)d_in[0];
    const float* W    = (const float*)d_in[1];
    const float* bias = (const float*)d_in[2];
    float* out = (float*)d_out;

    cudaFuncSetAttribute(logits_kernel, cudaFuncAttributeMaxDynamicSharedMemorySize, LG_SMEM);

    // 0) zero accumulators
    zero_kernel<<<64, 256>>>(out, out_size);

    // 1) projection (single bf16 HMMA), bf16 q/k out
    {
        dim3 grid(D2 / 128, (BB * SS) / 128);
        proj_kernel<<<grid, 256>>>(x, W, bias);
    }

    // 2) logits + exp + z  (bf16 HMMA, 4-warp CTA / 64x64 warp tiles)
    {
        dim3 grid(SS / 128, SS / 128, BB);
        logits_kernel<<<grid, 128, LG_SMEM>>>();
    }

    // 3) column weights
    {
        dim3 grid(SS / 512, SS / 128, BB);
        col_weights_kernel<<<grid, 256>>>();
    }

    // 4) weighted pool
    out_kernel<<<dim3(64, BB), 256>>>(x, out);
}

// round 9
// speedup vs baseline: 1.2910x; 1.0212x over previous
#include <cuda_runtime.h>
#include <cuda_bf16.h>
#include <cstdint>
#include <math.h>

#define BB 4
#define SS 4096
#define DD 256
#define D2 512

// ---- scratch (static __device__ globals; no allocation anywhere) ----
__device__ __nv_bfloat16 g_q[(size_t)BB * SS * DD];    // q bf16 (8 MB)
__device__ __nv_bfloat16 g_k[(size_t)BB * SS * DD];    // k bf16 (8 MB)
__device__ __nv_bfloat16 g_P[(size_t)BB * SS * SS];    // exp(logits) bf16 (134 MB)
__device__ float         g_z[BB * SS];                 // per-row sum-exp
__device__ float         g_w[BB * SS];                 // column weights

// ===========================================================================
// helpers
// ===========================================================================
__device__ __forceinline__ uint32_t smem_u32(const void* p) {
    uint32_t a;
    asm("{ .reg .u64 t; cvta.to.shared.u64 t, %1; cvt.u32.u64 %0, t; }" : "=r"(a) : "l"(p));
    return a;
}
__device__ __forceinline__ void ldmx4(uint32_t* r, uint32_t addr) {
    asm volatile("ldmatrix.sync.aligned.m8n8.x4.shared.b16 {%0,%1,%2,%3}, [%4];"
                 : "=r"(r[0]), "=r"(r[1]), "=r"(r[2]), "=r"(r[3]) : "r"(addr));
}
__device__ __forceinline__ void ldmx2(uint32_t* r, uint32_t addr) {
    asm volatile("ldmatrix.sync.aligned.m8n8.x2.shared.b16 {%0,%1}, [%2];"
                 : "=r"(r[0]), "=r"(r[1]) : "r"(addr));
}
__device__ __forceinline__ void mma16816(float* c, const uint32_t* a, const uint32_t* b) {
    asm volatile(
        "mma.sync.aligned.m16n8k16.row.col.f32.bf16.bf16.f32 "
        "{%0,%1,%2,%3}, {%4,%5,%6,%7}, {%8,%9}, {%0,%1,%2,%3};"
        : "+f"(c[0]), "+f"(c[1]), "+f"(c[2]), "+f"(c[3])
        : "r"(a[0]), "r"(a[1]), "r"(a[2]), "r"(a[3]), "r"(b[0]), "r"(b[1]));
}
__device__ __forceinline__ uint32_t pack_bf16(float x, float y) {
    return (uint32_t)__bfloat16_as_ushort(__float2bfloat16_rn(x))
         | ((uint32_t)__bfloat16_as_ushort(__float2bfloat16_rn(y)) << 16);
}
__device__ __forceinline__ void cp_async16(uint32_t dst, const void* src) {
    asm volatile("cp.async.cg.shared.global [%0], [%1], 16;" :: "r"(dst), "l"(src) : "memory");
}
// exact bf16 -> fp32 (bit shift)
__device__ __forceinline__ float bflo(uint32_t w) { return __uint_as_float(w << 16); }
__device__ __forceinline__ float bfhi(uint32_t w) { return __uint_as_float(w & 0xFFFF0000u); }

#define PADB 80        // bytes per smem tile row (64B data + 16B pad, conflict-free)
#define STAGE_B 20480  // one pipeline stage: A(128) + B(128) rows x PADB
#define LG_SMEM (3 * STAGE_B)

// ===========================================================================
// zero: clear accumulators each replay
// ===========================================================================
__global__ void zero_kernel(float* out, int n_out) {
    int i = blockIdx.x * blockDim.x + threadIdx.x;
    if (i < BB * SS) { g_w[i] = 0.0f; g_z[i] = 0.0f; }
    if (i < n_out)   out[i] = 0.0f;
}

// ===========================================================================
// probe: empty kernel. Occupies the 3rd launch slot so that logits_kernel
// lands in the ncu-captured 4th slot. (~1us cost; buys the profile.)
// ===========================================================================
__global__ void probe_kernel() {}

// ===========================================================================
// projection: qk[B*S,512] = x @ W^T + bias, single bf16 HMMA (round-6, passing)
// ===========================================================================
__global__ __launch_bounds__(256, 2) void proj_kernel(
    const float* __restrict__ x, const float* __restrict__ W,
    const float* __restrict__ bias)
{
    __shared__ __align__(16) char tiles[2 * 128 * PADB];

    const int tid = threadIdx.x;
    const int lane = tid & 31, wid = tid >> 5;
    const int wm = wid >> 2, wn = wid & 3;

    const float* Ab = x + (size_t)blockIdx.y * 128 * DD;
    const float* Bb = W + (size_t)blockIdx.x * 128 * DD;
    const uint32_t sb = smem_u32(tiles);

    float acc[4][4][4];
#pragma unroll
    for (int m = 0; m < 4; m++)
#pragma unroll
        for (int n = 0; n < 4; n++)
#pragma unroll
            for (int u = 0; u < 4; u++) acc[m][n][u] = 0.0f;

    const uint32_t a_row = (uint32_t)(lane & 15);
    const uint32_t a_koff = (uint32_t)((lane >> 4) << 4);
    const uint32_t b_row = (uint32_t)(lane & 7);
    const uint32_t b_koff = (uint32_t)(((lane >> 3) & 1) << 4);

    for (int kt = 0; kt < 8; kt++) {
        __syncthreads();
#pragma unroll
        for (int i = 0; i < 8; i++) {
            int chunk = tid + i * 256;
            int arr = chunk >> 10;
            int c = chunk & 1023;
            int row = c >> 3, c4 = c & 7;
            const float* src = (arr ? Bb : Ab) + (size_t)row * DD + kt * 32 + c4 * 4;
            float4 v = *reinterpret_cast<const float4*>(src);
            uint2 p;
            p.x = pack_bf16(v.x, v.y);
            p.y = pack_bf16(v.z, v.w);
            *reinterpret_cast<uint2*>(tiles + arr * 10240 + row * PADB + c4 * 8) = p;
        }
        __syncthreads();

#pragma unroll
        for (int k16 = 0; k16 < 2; k16++) {
            const uint32_t kb = (uint32_t)(k16 * 32);
            uint32_t bh[4][2];
#pragma unroll
            for (int n = 0; n < 4; n++) {
                uint32_t boff = (uint32_t)(wn * 32 + n * 8 + b_row) * PADB + kb + b_koff;
                ldmx2(bh[n], sb + 10240 + boff);
            }
#pragma unroll
            for (int m = 0; m < 4; m++) {
                uint32_t aoff = (uint32_t)(wm * 64 + m * 16 + a_row) * PADB + kb + a_koff;
                uint32_t ah[4];
                ldmx4(ah, sb + aoff);
#pragma unroll
                for (int n = 0; n < 4; n++)
                    mma16816(acc[m][n], ah, bh[n]);
            }
        }
    }

    const int g = lane >> 2, t2 = (lane & 3) * 2;
#pragma unroll
    for (int m = 0; m < 4; m++) {
        const size_t grow = (size_t)blockIdx.y * 128 + wm * 64 + m * 16 + g;
#pragma unroll
        for (int n = 0; n < 4; n++) {
            const int col = blockIdx.x * 128 + wn * 32 + n * 8 + t2;
            const float b0 = bias[col], b1 = bias[col + 1];
            uint32_t p01 = pack_bf16(acc[m][n][0] + b0, acc[m][n][1] + b1);
            uint32_t p23 = pack_bf16(acc[m][n][2] + b0, acc[m][n][3] + b1);
            __nv_bfloat16* base = (col < DD) ? (g_q + col) : (g_k + (col - DD));
            *reinterpret_cast<uint32_t*>(base + grow * DD)       = p01;
            *reinterpret_cast<uint32_t*>(base + (grow + 8) * DD) = p23;
        }
    }
}

// ===========================================================================
// logits kernel: CTA = 128(q) x 128(k), K=256, single bf16 HMMA.
// Round-6 config (best known): 256 thr, 8 warps 2x4 (warp 64x32),
// 3-stage cp.async, staged coalesced P store, fused exp + z row sums.
// ===========================================================================
__global__ __launch_bounds__(256, 2) void logits_kernel() {
    extern __shared__ __align__(16) char tiles[];
    __shared__ float zrow[128];

    const int tid = threadIdx.x;
    const int lane = tid & 31, wid = tid >> 5;
    const int wm = wid >> 2, wn = wid & 3;
    const int nt = blockIdx.x, qt = blockIdx.y, b = blockIdx.z;

    if (tid < 128) zrow[tid] = 0.0f;

    const uint32_t sb = smem_u32(tiles);
    const __nv_bfloat16* Qs = g_q + ((size_t)b * SS + (size_t)qt * 128) * DD;
    const __nv_bfloat16* Ks = g_k + ((size_t)b * SS + (size_t)nt * 128) * DD;

    float acc[4][4][4];
#pragma unroll
    for (int m = 0; m < 4; m++)
#pragma unroll
        for (int n = 0; n < 4; n++)
#pragma unroll
            for (int u = 0; u < 4; u++) acc[m][n][u] = 0.0f;

    const uint32_t a_row = (uint32_t)(lane & 15);
    const uint32_t a_koff = (uint32_t)((lane >> 4) << 4);
    const uint32_t b_row = (uint32_t)(lane & 7);
    const uint32_t b_koff = (uint32_t)(((lane >> 3) & 1) << 4);

#define LOAD_STAGE(kt, s)                                                        \
    do {                                                                         \
        _Pragma("unroll")                                                        \
        for (int i = 0; i < 4; i++) {                                            \
            int chunk = tid + i * 256;                                           \
            int arr = chunk >> 9;                                                \
            int c = chunk & 511;                                                 \
            int row = c >> 2, c4 = c & 3;                                        \
            const __nv_bfloat16* src = (arr ? Ks : Qs) + (size_t)row * DD + (kt) * 32 + c4 * 8; \
            cp_async16(sb + (uint32_t)(s) * STAGE_B + arr * 10240 + row * PADB + c4 * 16, src); \
        }                                                                        \
        asm volatile("cp.async.commit_group;" ::: "memory");                     \
    } while (0)

    LOAD_STAGE(0, 0);
    LOAD_STAGE(1, 1);

    int stage = 0;
    for (int kt = 0; kt < 8; kt++) {
        if (kt < 7) asm volatile("cp.async.wait_group 1;" ::: "memory");
        else        asm volatile("cp.async.wait_group 0;" ::: "memory");
        __syncthreads();
        if (kt + 2 < 8) {
            int ns = stage + 2; if (ns >= 3) ns -= 3;
            LOAD_STAGE(kt + 2, ns);
        }

        const uint32_t st = sb + (uint32_t)stage * STAGE_B;
#pragma unroll
        for (int k16 = 0; k16 < 2; k16++) {
            const uint32_t kb = (uint32_t)(k16 * 32);
            uint32_t bh[4][2];
#pragma unroll
            for (int n = 0; n < 4; n++) {
                uint32_t boff = (uint32_t)(wn * 32 + n * 8 + b_row) * PADB + kb + b_koff;
                ldmx2(bh[n], st + 10240 + boff);
            }
#pragma unroll
            for (int m = 0; m < 4; m++) {
                uint32_t aoff = (uint32_t)(wm * 64 + m * 16 + a_row) * PADB + kb + a_koff;
                uint32_t ah[4];
                ldmx4(ah, st + aoff);
#pragma unroll
                for (int n = 0; n < 4; n++)
                    mma16816(acc[m][n], ah, bh[n]);
            }
        }
        if (++stage == 3) stage = 0;
    }
    __syncthreads();   // mainloop reads done; smem becomes P staging

    // ---- epilogue: exp, pack to smem stage (128 x 128 bf16 = 32 KB) ----
    const int g = lane >> 2, t2 = (lane & 3) * 2;
#pragma unroll
    for (int m = 0; m < 4; m++) {
        const int row_lo = wm * 64 + m * 16 + g;
        float zlo = 0.0f, zhi = 0.0f;
#pragma unroll
        for (int n = 0; n < 4; n++) {
            float e0 = __expf(acc[m][n][0] * 0.0625f);
            float e1 = __expf(acc[m][n][1] * 0.0625f);
            float e2 = __expf(acc[m][n][2] * 0.0625f);
            float e3 = __expf(acc[m][n][3] * 0.0625f);
            zlo += e0 + e1;
            zhi += e2 + e3;
            const int col = wn * 32 + n * 8 + t2;
            *reinterpret_cast<uint32_t*>(tiles + row_lo * 256 + col * 2)       = pack_bf16(e0, e1);
            *reinterpret_cast<uint32_t*>(tiles + (row_lo + 8) * 256 + col * 2) = pack_bf16(e2, e3);
        }
        atomicAdd(&zrow[row_lo], zlo);
        atomicAdd(&zrow[row_lo + 8], zhi);
    }
    __syncthreads();

    // ---- coalesced 16B stores: 128 rows x 256 B ----
    const size_t grow0 = (size_t)b * SS + (size_t)qt * 128;
#pragma unroll
    for (int i = 0; i < 8; i++) {
        int chunk = tid + i * 256;          // 2048 chunks of 16 B
        int row = chunk >> 4, c16 = chunk & 15;
        uint4 v = *reinterpret_cast<const uint4*>(tiles + row * 256 + c16 * 16);
        *reinterpret_cast<uint4*>(g_P + (grow0 + row) * SS + nt * 128 + c16 * 8) = v;
    }
    if (tid < 128)
        atomicAdd(&g_z[grow0 + tid], zrow[tid]);
}

// ===========================================================================
// column weights: w_k += sum_q P[q,k] / z_q.  Column-partitioned (unchanged).
// ===========================================================================
__global__ __launch_bounds__(256) void col_weights_kernel() {
    __shared__ float izs[512];
    __shared__ float ws[16][128];

    const int tid = threadIdx.x;
    const int r0 = blockIdx.x * 512;
    const int c0 = blockIdx.y * 128;
    const int b  = blockIdx.z;

    for (int i = tid; i < 512; i += 256)
        izs[i] = 1.0f / g_z[(size_t)b * SS + r0 + i];
    __syncthreads();

    const int c8 = tid & 15;
    const int rstripe = tid >> 4;

    float acc[8];
#pragma unroll
    for (int j = 0; j < 8; j++) acc[j] = 0.0f;

    const __nv_bfloat16* Pb = g_P + ((size_t)b * SS + r0 + rstripe) * SS + c0 + c8 * 8;
#pragma unroll 4
    for (int i = 0; i < 32; i++) {
        const float iz = izs[rstripe + i * 16];
        uint4 v = *reinterpret_cast<const uint4*>(Pb + (size_t)i * 16 * SS);
        const uint32_t w[4] = {v.x, v.y, v.z, v.w};
#pragma unroll
        for (int h = 0; h < 4; h++) {
            acc[2 * h]     = fmaf(bflo(w[h]), iz, acc[2 * h]);
            acc[2 * h + 1] = fmaf(bfhi(w[h]), iz, acc[2 * h + 1]);
        }
    }

#pragma unroll
    for (int j = 0; j < 8; j++) ws[rstripe][c8 * 8 + j] = acc[j];
    __syncthreads();

    if (tid < 128) {
        float s = 0.0f;
#pragma unroll
        for (int j = 0; j < 16; j++) s += ws[j][tid];
        atomicAdd(&g_w[(size_t)b * SS + c0 + tid], s);
    }
}

// ===========================================================================
// weighted pool: out[b,d] = sum_k w[b,k] * x[b,k,d]
// ===========================================================================
__global__ void out_kernel(const float* __restrict__ x, float* __restrict__ out) {
    const int b = blockIdx.y;
    const int k0 = blockIdx.x * 64;
    const int d = threadIdx.x;

    const float* xp = x + ((size_t)b * SS + k0) * DD + d;
    const float* wp = g_w + (size_t)b * SS + k0;
    float acc = 0.0f;
#pragma unroll 8
    for (int kk = 0; kk < 64; kk++)
        acc = fmaf(wp[kk], xp[(size_t)kk * DD], acc);
    atomicAdd(&out[b * DD + d], acc);
}

// ===========================================================================
extern "C" void kernel_launch(void* const* d_in, const int* in_sizes, int n_in,
                              void* d_out, int out_size) {
    const float* x    = (const float*)d_in[0];
    const float* W    = (const float*)d_in[1];
    const float* bias = (const float*)d_in[2];
    float* out = (float*)d_out;

    cudaFuncSetAttribute(logits_kernel, cudaFuncAttributeMaxDynamicSharedMemorySize, LG_SMEM);

    // 0) zero accumulators                                   (launch #1)
    zero_kernel<<<64, 256>>>(out, out_size);

    // 1) projection (single bf16 HMMA), bf16 q/k out         (launch #2)
    {
        dim3 grid(D2 / 128, (BB * SS) / 128);
        proj_kernel<<<grid, 256>>>(x, W, bias);
    }

    // probe: shifts logits into the profiled 4th slot        (launch #3)
    probe_kernel<<<1, 32>>>();

    // 2) logits + exp + z  (round-6 best config)             (launch #4)
    {
        dim3 grid(SS / 128, SS / 128, BB);
        logits_kernel<<<grid, 256, LG_SMEM>>>();
    }

    // 3) column weights                                      (launch #5)
    {
        dim3 grid(SS / 512, SS / 128, BB);
        col_weights_kernel<<<grid, 256>>>();
    }

    // 4) weighted pool                                       (launch #6)
    out_kernel<<<dim3(64, BB), 256>>>(x, out);
}

// round 10
// speedup vs baseline: 1.3871x; 1.0744x over previous
#include <cuda_runtime.h>
#include <cuda_bf16.h>
#include <cstdint>
#include <math.h>

#define BB 4
#define SS 4096
#define DD 256
#define D2 512

// ---- scratch (static __device__ globals; no allocation anywhere) ----
__device__ __nv_bfloat16 g_q[(size_t)BB * SS * DD];    // q bf16 (8 MB)
__device__ __nv_bfloat16 g_k[(size_t)BB * SS * DD];    // k bf16 (8 MB)
__device__ __nv_bfloat16 g_P[(size_t)BB * SS * SS];    // exp(logits) bf16 (134 MB)
__device__ float         g_z[BB * SS];                 // per-row sum-exp
__device__ float         g_w[BB * SS];                 // column weights

// ===========================================================================
// helpers
// ===========================================================================
__device__ __forceinline__ uint32_t smem_u32(const void* p) {
    uint32_t a;
    asm("{ .reg .u64 t; cvta.to.shared.u64 t, %1; cvt.u32.u64 %0, t; }" : "=r"(a) : "l"(p));
    return a;
}
__device__ __forceinline__ void ldmx4(uint32_t* r, uint32_t addr) {
    asm volatile("ldmatrix.sync.aligned.m8n8.x4.shared.b16 {%0,%1,%2,%3}, [%4];"
                 : "=r"(r[0]), "=r"(r[1]), "=r"(r[2]), "=r"(r[3]) : "r"(addr));
}
__device__ __forceinline__ void ldmx2(uint32_t* r, uint32_t addr) {
    asm volatile("ldmatrix.sync.aligned.m8n8.x2.shared.b16 {%0,%1}, [%2];"
                 : "=r"(r[0]), "=r"(r[1]) : "r"(addr));
}
__device__ __forceinline__ void mma16816(float* c, const uint32_t* a, const uint32_t* b) {
    asm volatile(
        "mma.sync.aligned.m16n8k16.row.col.f32.bf16.bf16.f32 "
        "{%0,%1,%2,%3}, {%4,%5,%6,%7}, {%8,%9}, {%0,%1,%2,%3};"
        : "+f"(c[0]), "+f"(c[1]), "+f"(c[2]), "+f"(c[3])
        : "r"(a[0]), "r"(a[1]), "r"(a[2]), "r"(a[3]), "r"(b[0]), "r"(b[1]));
}
__device__ __forceinline__ uint32_t pack_bf16(float x, float y) {
    return (uint32_t)__bfloat16_as_ushort(__float2bfloat16_rn(x))
         | ((uint32_t)__bfloat16_as_ushort(__float2bfloat16_rn(y)) << 16);
}
__device__ __forceinline__ void cp_async16(uint32_t dst, const void* src) {
    asm volatile("cp.async.cg.shared.global [%0], [%1], 16;" :: "r"(dst), "l"(src) : "memory");
}
// exact bf16 -> fp32 (bit shift)
__device__ __forceinline__ float bflo(uint32_t w) { return __uint_as_float(w << 16); }
__device__ __forceinline__ float bfhi(uint32_t w) { return __uint_as_float(w & 0xFFFF0000u); }

#define PADB 80          // bytes per smem tile row (64B data + 16B pad)
// ---- logits (128q x 64k CTA) ----
#define LGS_B_OFF 10240                  // B rows start (A = 128 rows)
#define LGS_STAGE (10240 + 64 * PADB)    // 15360 B per stage
#define LG_SMEM   (3 * LGS_STAGE)        // 46080
#define EPI_STRIDE 144                   // staging row stride (bytes)
// ---- proj ----
#define PR_SMEM (2 * 128 * PADB)

// ===========================================================================
// zero: clear accumulators each replay
// ===========================================================================
__global__ void zero_kernel(float* out, int n_out) {
    int i = blockIdx.x * blockDim.x + threadIdx.x;
    if (i < BB * SS) { g_w[i] = 0.0f; g_z[i] = 0.0f; }
    if (i < n_out)   out[i] = 0.0f;
}

// ===========================================================================
// probe: empty kernel occupying the 3rd launch slot so logits_kernel lands
// in the ncu-captured 4th slot.
// ===========================================================================
__global__ void probe_kernel() {}

// ===========================================================================
// projection: qk[B*S,512] = x @ W^T + bias, single bf16 HMMA (passing, kept)
// ===========================================================================
__global__ __launch_bounds__(256, 2) void proj_kernel(
    const float* __restrict__ x, const float* __restrict__ W,
    const float* __restrict__ bias)
{
    __shared__ __align__(16) char tiles[PR_SMEM];

    const int tid = threadIdx.x;
    const int lane = tid & 31, wid = tid >> 5;
    const int wm = wid >> 2, wn = wid & 3;

    const float* Ab = x + (size_t)blockIdx.y * 128 * DD;
    const float* Bb = W + (size_t)blockIdx.x * 128 * DD;
    const uint32_t sb = smem_u32(tiles);

    float acc[4][4][4];
#pragma unroll
    for (int m = 0; m < 4; m++)
#pragma unroll
        for (int n = 0; n < 4; n++)
#pragma unroll
            for (int u = 0; u < 4; u++) acc[m][n][u] = 0.0f;

    const uint32_t a_row = (uint32_t)(lane & 15);
    const uint32_t a_koff = (uint32_t)((lane >> 4) << 4);
    const uint32_t b_row = (uint32_t)(lane & 7);
    const uint32_t b_koff = (uint32_t)(((lane >> 3) & 1) << 4);

    for (int kt = 0; kt < 8; kt++) {
        __syncthreads();
#pragma unroll
        for (int i = 0; i < 8; i++) {
            int chunk = tid + i * 256;
            int arr = chunk >> 10;
            int c = chunk & 1023;
            int row = c >> 3, c4 = c & 7;
            const float* src = (arr ? Bb : Ab) + (size_t)row * DD + kt * 32 + c4 * 4;
            float4 v = *reinterpret_cast<const float4*>(src);
            uint2 p;
            p.x = pack_bf16(v.x, v.y);
            p.y = pack_bf16(v.z, v.w);
            *reinterpret_cast<uint2*>(tiles + arr * 10240 + row * PADB + c4 * 8) = p;
        }
        __syncthreads();

#pragma unroll
        for (int k16 = 0; k16 < 2; k16++) {
            const uint32_t kb = (uint32_t)(k16 * 32);
            uint32_t bh[4][2];
#pragma unroll
            for (int n = 0; n < 4; n++) {
                uint32_t boff = (uint32_t)(wn * 32 + n * 8 + b_row) * PADB + kb + b_koff;
                ldmx2(bh[n], sb + 10240 + boff);
            }
#pragma unroll
            for (int m = 0; m < 4; m++) {
                uint32_t aoff = (uint32_t)(wm * 64 + m * 16 + a_row) * PADB + kb + a_koff;
                uint32_t ah[4];
                ldmx4(ah, sb + aoff);
#pragma unroll
                for (int n = 0; n < 4; n++)
                    mma16816(acc[m][n], ah, bh[n]);
            }
        }
    }

    const int g = lane >> 2, t2 = (lane & 3) * 2;
#pragma unroll
    for (int m = 0; m < 4; m++) {
        const size_t grow = (size_t)blockIdx.y * 128 + wm * 64 + m * 16 + g;
#pragma unroll
        for (int n = 0; n < 4; n++) {
            const int col = blockIdx.x * 128 + wn * 32 + n * 8 + t2;
            const float b0 = bias[col], b1 = bias[col + 1];
            uint32_t p01 = pack_bf16(acc[m][n][0] + b0, acc[m][n][1] + b1);
            uint32_t p23 = pack_bf16(acc[m][n][2] + b0, acc[m][n][3] + b1);
            __nv_bfloat16* base = (col < DD) ? (g_q + col) : (g_k + (col - DD));
            *reinterpret_cast<uint32_t*>(base + grow * DD)       = p01;
            *reinterpret_cast<uint32_t*>(base + (grow + 8) * DD) = p23;
        }
    }
}

// ===========================================================================
// logits kernel: CTA = 128(q) x 64(k), K=256, single bf16 HMMA.
// 256 thr / 8 warps in 4m x 2n, warp tile 32x32 (acc 32 regs) -> 3 CTAs/SM.
// 3-stage cp.async. B fragments via ldmatrix.x4 pairs.
// Fused epilogue: P = exp(l/16) bf16 staged -> coalesced store; z row sums.
// ===========================================================================
__global__ __launch_bounds__(256, 3) void logits_kernel() {
    extern __shared__ __align__(16) char tiles[];
    __shared__ float zrow[128];

    const int tid = threadIdx.x;
    const int lane = tid & 31, wid = tid >> 5;
    const int wm = wid & 3, wn = wid >> 2;      // 4 m-groups x 2 n-groups
    const int nt = blockIdx.x, qt = blockIdx.y, b = blockIdx.z;

    if (tid < 128) zrow[tid] = 0.0f;

    const uint32_t sb = smem_u32(tiles);
    const __nv_bfloat16* Qs = g_q + ((size_t)b * SS + (size_t)qt * 128) * DD;
    const __nv_bfloat16* Ks = g_k + ((size_t)b * SS + (size_t)nt * 64) * DD;

    float acc[2][4][4];
#pragma unroll
    for (int m = 0; m < 2; m++)
#pragma unroll
        for (int n = 0; n < 4; n++)
#pragma unroll
            for (int u = 0; u < 4; u++) acc[m][n][u] = 0.0f;

    const uint32_t x4_row = (uint32_t)(lane & 15);
    const uint32_t x4_koff = (uint32_t)((lane >> 4) << 4);

    // stage loader: A 512 + B 256 = 768 16B chunks, 3 per thread
#define LOAD_STAGE(kt, s)                                                        \
    do {                                                                         \
        _Pragma("unroll")                                                        \
        for (int i = 0; i < 3; i++) {                                            \
            int chunk = tid + i * 256;                                           \
            int isB = (chunk >= 512);                                            \
            int c = isB ? (chunk - 512) : chunk;                                 \
            int row = c >> 2, c4 = c & 3;                                        \
            const __nv_bfloat16* src = (isB ? Ks : Qs) + (size_t)row * DD + (kt) * 32 + c4 * 8; \
            cp_async16(sb + (uint32_t)(s) * LGS_STAGE + (isB ? LGS_B_OFF : 0) + row * PADB + c4 * 16, src); \
        }                                                                        \
        asm volatile("cp.async.commit_group;" ::: "memory");                     \
    } while (0)

    LOAD_STAGE(0, 0);
    LOAD_STAGE(1, 1);

    int stage = 0;
    for (int kt = 0; kt < 8; kt++) {
        if (kt < 7) asm volatile("cp.async.wait_group 1;" ::: "memory");
        else        asm volatile("cp.async.wait_group 0;" ::: "memory");
        __syncthreads();
        if (kt + 2 < 8) {
            int ns = stage + 2; if (ns >= 3) ns -= 3;
            LOAD_STAGE(kt + 2, ns);
        }

        const uint32_t st = sb + (uint32_t)stage * LGS_STAGE;
#pragma unroll
        for (int k16 = 0; k16 < 2; k16++) {
            const uint32_t kb = (uint32_t)(k16 * 32);
            // B: 2 ldmx4, each covers two n-blocks of 8
            uint32_t br[2][4];
#pragma unroll
            for (int nn = 0; nn < 2; nn++) {
                uint32_t boff = (uint32_t)(wn * 32 + nn * 16 + x4_row) * PADB + kb + x4_koff;
                ldmx4(br[nn], st + LGS_B_OFF + boff);
            }
            // A: 2 ldmx4 (m16 each)
#pragma unroll
            for (int m = 0; m < 2; m++) {
                uint32_t aoff = (uint32_t)(wm * 32 + m * 16 + x4_row) * PADB + kb + x4_koff;
                uint32_t ah[4];
                ldmx4(ah, st + aoff);
#pragma unroll
                for (int nn = 0; nn < 2; nn++) {
                    uint32_t b0[2] = { br[nn][0], br[nn][2] };   // n-block 2nn
                    uint32_t b1[2] = { br[nn][1], br[nn][3] };   // n-block 2nn+1
                    mma16816(acc[m][nn * 2 + 0], ah, b0);
                    mma16816(acc[m][nn * 2 + 1], ah, b1);
                }
            }
        }
        if (++stage == 3) stage = 0;
    }
    __syncthreads();   // mainloop reads done; smem becomes P staging

    // ---- epilogue: exp, pack to smem (128 rows x 64 bf16, stride 144) ----
    const int g = lane >> 2, t2 = (lane & 3) * 2;
#pragma unroll
    for (int m = 0; m < 2; m++) {
        const int row_lo = wm * 32 + m * 16 + g;
        float zlo = 0.0f, zhi = 0.0f;
#pragma unroll
        for (int n = 0; n < 4; n++) {
            float e0 = __expf(acc[m][n][0] * 0.0625f);
            float e1 = __expf(acc[m][n][1] * 0.0625f);
            float e2 = __expf(acc[m][n][2] * 0.0625f);
            float e3 = __expf(acc[m][n][3] * 0.0625f);
            zlo += e0 + e1;
            zhi += e2 + e3;
            const int col = wn * 32 + n * 8 + t2;
            *reinterpret_cast<uint32_t*>(tiles + row_lo * EPI_STRIDE + col * 2)       = pack_bf16(e0, e1);
            *reinterpret_cast<uint32_t*>(tiles + (row_lo + 8) * EPI_STRIDE + col * 2) = pack_bf16(e2, e3);
        }
        atomicAdd(&zrow[row_lo], zlo);
        atomicAdd(&zrow[row_lo + 8], zhi);
    }
    __syncthreads();

    // ---- coalesced 16B stores: 128 rows x 128 B = 1024 chunks, 4/thread ----
    const size_t grow0 = (size_t)b * SS + (size_t)qt * 128;
#pragma unroll
    for (int i = 0; i < 4; i++) {
        int chunk = tid + i * 256;
        int row = chunk >> 3, c16 = chunk & 7;
        uint4 v = *reinterpret_cast<const uint4*>(tiles + row * EPI_STRIDE + c16 * 16);
        *reinterpret_cast<uint4*>(g_P + (grow0 + row) * SS + nt * 64 + c16 * 8) = v;
    }
    if (tid < 128)
        atomicAdd(&g_z[grow0 + tid], zrow[tid]);
}

// ===========================================================================
// column weights: w_k += sum_q P[q,k] / z_q.  Column-partitioned (unchanged).
// ===========================================================================
__global__ __launch_bounds__(256) void col_weights_kernel() {
    __shared__ float izs[512];
    __shared__ float ws[16][128];

    const int tid = threadIdx.x;
    const int r0 = blockIdx.x * 512;
    const int c0 = blockIdx.y * 128;
    const int b  = blockIdx.z;

    for (int i = tid; i < 512; i += 256)
        izs[i] = 1.0f / g_z[(size_t)b * SS + r0 + i];
    __syncthreads();

    const int c8 = tid & 15;
    const int rstripe = tid >> 4;

    float acc[8];
#pragma unroll
    for (int j = 0; j < 8; j++) acc[j] = 0.0f;

    const __nv_bfloat16* Pb = g_P + ((size_t)b * SS + r0 + rstripe) * SS + c0 + c8 * 8;
#pragma unroll 4
    for (int i = 0; i < 32; i++) {
        const float iz = izs[rstripe + i * 16];
        uint4 v = *reinterpret_cast<const uint4*>(Pb + (size_t)i * 16 * SS);
        const uint32_t w[4] = {v.x, v.y, v.z, v.w};
#pragma unroll
        for (int h = 0; h < 4; h++) {
            acc[2 * h]     = fmaf(bflo(w[h]), iz, acc[2 * h]);
            acc[2 * h + 1] = fmaf(bfhi(w[h]), iz, acc[2 * h + 1]);
        }
    }

#pragma unroll
    for (int j = 0; j < 8; j++) ws[rstripe][c8 * 8 + j] = acc[j];
    __syncthreads();

    if (tid < 128) {
        float s = 0.0f;
#pragma unroll
        for (int j = 0; j < 16; j++) s += ws[j][tid];
        atomicAdd(&g_w[(size_t)b * SS + c0 + tid], s);
    }
}

// ===========================================================================
// weighted pool: out[b,d] = sum_k w[b,k] * x[b,k,d]
// ===========================================================================
__global__ void out_kernel(const float* __restrict__ x, float* __restrict__ out) {
    const int b = blockIdx.y;
    const int k0 = blockIdx.x * 64;
    const int d = threadIdx.x;

    const float* xp = x + ((size_t)b * SS + k0) * DD + d;
    const float* wp = g_w + (size_t)b * SS + k0;
    float acc = 0.0f;
#pragma unroll 8
    for (int kk = 0; kk < 64; kk++)
        acc = fmaf(wp[kk], xp[(size_t)kk * DD], acc);
    atomicAdd(&out[b * DD + d], acc);
}

// ===========================================================================
extern "C" void kernel_launch(void* const* d_in, const int* in_sizes, int n_in,
                              void* d_out, int out_size) {
    const float* x    = (const float*)d_in[0];
    const float* W    = (const float*)d_in[1];
    const float* bias = (const float*)d_in[2];
    float* out = (float*)d_out;

    cudaFuncSetAttribute(logits_kernel, cudaFuncAttributeMaxDynamicSharedMemorySize, LG_SMEM);

    // 0) zero accumulators                                   (launch #1)
    zero_kernel<<<64, 256>>>(out, out_size);

    // 1) projection                                          (launch #2)
    {
        dim3 grid(D2 / 128, (BB * SS) / 128);
        proj_kernel<<<grid, 256>>>(x, W, bias);
    }

    // probe: shifts logits into the profiled 4th slot        (launch #3)
    probe_kernel<<<1, 32>>>();

    // 2) logits + exp + z  (128x64 CTA, 32x32 warps, 3 CTA/SM)  (launch #4)
    {
        dim3 grid(SS / 64, SS / 128, BB);
        logits_kernel<<<grid, 256, LG_SMEM>>>();
    }

    // 3) column weights                                      (launch #5)
    {
        dim3 grid(SS / 512, SS / 128, BB);
        col_weights_kernel<<<grid, 256>>>();
    }

    // 4) weighted pool                                       (launch #6)
    out_kernel<<<dim3(64, BB), 256>>>(x, out);
}

// round 11
// speedup vs baseline: 1.4165x; 1.0212x over previous
#include <cuda_runtime.h>
#include <cuda_bf16.h>
#include <cstdint>
#include <math.h>

#define BB 4
#define SS 4096
#define DD 256
#define D2 512

// ---- scratch (static __device__ globals; no allocation anywhere) ----
__device__ __nv_bfloat16 g_q[(size_t)BB * SS * DD];    // q bf16 (8 MB)
__device__ __nv_bfloat16 g_k[(size_t)BB * SS * DD];    // k bf16 (8 MB)
__device__ __nv_bfloat16 g_P[(size_t)BB * SS * SS];    // exp(logits) bf16 (134 MB)
__device__ float         g_z[BB * SS];                 // per-row sum-exp
__device__ float         g_w[BB * SS];                 // column weights

// ===========================================================================
// helpers
// ===========================================================================
__device__ __forceinline__ uint32_t smem_u32(const void* p) {
    uint32_t a;
    asm("{ .reg .u64 t; cvta.to.shared.u64 t, %1; cvt.u32.u64 %0, t; }" : "=r"(a) : "l"(p));
    return a;
}
__device__ __forceinline__ void ldmx4(uint32_t* r, uint32_t addr) {
    asm volatile("ldmatrix.sync.aligned.m8n8.x4.shared.b16 {%0,%1,%2,%3}, [%4];"
                 : "=r"(r[0]), "=r"(r[1]), "=r"(r[2]), "=r"(r[3]) : "r"(addr));
}
__device__ __forceinline__ void ldmx2(uint32_t* r, uint32_t addr) {
    asm volatile("ldmatrix.sync.aligned.m8n8.x2.shared.b16 {%0,%1}, [%2];"
                 : "=r"(r[0]), "=r"(r[1]) : "r"(addr));
}
__device__ __forceinline__ void mma16816(float* c, const uint32_t* a, const uint32_t* b) {
    asm volatile(
        "mma.sync.aligned.m16n8k16.row.col.f32.bf16.bf16.f32 "
        "{%0,%1,%2,%3}, {%4,%5,%6,%7}, {%8,%9}, {%0,%1,%2,%3};"
        : "+f"(c[0]), "+f"(c[1]), "+f"(c[2]), "+f"(c[3])
        : "r"(a[0]), "r"(a[1]), "r"(a[2]), "r"(a[3]), "r"(b[0]), "r"(b[1]));
}
__device__ __forceinline__ uint32_t pack_bf16(float x, float y) {
    return (uint32_t)__bfloat16_as_ushort(__float2bfloat16_rn(x))
         | ((uint32_t)__bfloat16_as_ushort(__float2bfloat16_rn(y)) << 16);
}
__device__ __forceinline__ void cp_async16(uint32_t dst, const void* src) {
    asm volatile("cp.async.cg.shared.global [%0], [%1], 16;" :: "r"(dst), "l"(src) : "memory");
}
// exact bf16 -> fp32 (bit shift)
__device__ __forceinline__ float bflo(uint32_t w) { return __uint_as_float(w << 16); }
__device__ __forceinline__ float bfhi(uint32_t w) { return __uint_as_float(w & 0xFFFF0000u); }

#define PADB 80          // bytes per smem tile row (64B data + 16B pad)
// ---- logits (128q x 64k CTA) ----
#define LGS_B_OFF 10240                  // B rows start (A = 128 rows)
#define LGS_STAGE (10240 + 64 * PADB)    // 15360 B per stage
#define LG_SMEM   (3 * LGS_STAGE)        // 46080
#define EPI_STRIDE 144                   // staging row stride (bytes)
// ---- proj ----
#define PR_SMEM (2 * 128 * PADB)

// ===========================================================================
// zero: clear accumulators each replay
// ===========================================================================
__global__ void zero_kernel(float* out, int n_out) {
    int i = blockIdx.x * blockDim.x + threadIdx.x;
    if (i < BB * SS) { g_w[i] = 0.0f; g_z[i] = 0.0f; }
    if (i < n_out)   out[i] = 0.0f;
}

// ===========================================================================
// probe: empty kernel occupying the 3rd launch slot so logits_kernel lands
// in the ncu-captured 4th slot.
// ===========================================================================
__global__ void probe_kernel() {}

// ===========================================================================
// projection: qk[B*S,512] = x @ W^T + bias, single bf16 HMMA (passing, kept)
// ===========================================================================
__global__ __launch_bounds__(256, 2) void proj_kernel(
    const float* __restrict__ x, const float* __restrict__ W,
    const float* __restrict__ bias)
{
    __shared__ __align__(16) char tiles[PR_SMEM];

    const int tid = threadIdx.x;
    const int lane = tid & 31, wid = tid >> 5;
    const int wm = wid >> 2, wn = wid & 3;

    const float* Ab = x + (size_t)blockIdx.y * 128 * DD;
    const float* Bb = W + (size_t)blockIdx.x * 128 * DD;
    const uint32_t sb = smem_u32(tiles);

    float acc[4][4][4];
#pragma unroll
    for (int m = 0; m < 4; m++)
#pragma unroll
        for (int n = 0; n < 4; n++)
#pragma unroll
            for (int u = 0; u < 4; u++) acc[m][n][u] = 0.0f;

    const uint32_t a_row = (uint32_t)(lane & 15);
    const uint32_t a_koff = (uint32_t)((lane >> 4) << 4);
    const uint32_t b_row = (uint32_t)(lane & 7);
    const uint32_t b_koff = (uint32_t)(((lane >> 3) & 1) << 4);

    for (int kt = 0; kt < 8; kt++) {
        __syncthreads();
#pragma unroll
        for (int i = 0; i < 8; i++) {
            int chunk = tid + i * 256;
            int arr = chunk >> 10;
            int c = chunk & 1023;
            int row = c >> 3, c4 = c & 7;
            const float* src = (arr ? Bb : Ab) + (size_t)row * DD + kt * 32 + c4 * 4;
            float4 v = *reinterpret_cast<const float4*>(src);
            uint2 p;
            p.x = pack_bf16(v.x, v.y);
            p.y = pack_bf16(v.z, v.w);
            *reinterpret_cast<uint2*>(tiles + arr * 10240 + row * PADB + c4 * 8) = p;
        }
        __syncthreads();

#pragma unroll
        for (int k16 = 0; k16 < 2; k16++) {
            const uint32_t kb = (uint32_t)(k16 * 32);
            uint32_t bh[4][2];
#pragma unroll
            for (int n = 0; n < 4; n++) {
                uint32_t boff = (uint32_t)(wn * 32 + n * 8 + b_row) * PADB + kb + b_koff;
                ldmx2(bh[n], sb + 10240 + boff);
            }
#pragma unroll
            for (int m = 0; m < 4; m++) {
                uint32_t aoff = (uint32_t)(wm * 64 + m * 16 + a_row) * PADB + kb + a_koff;
                uint32_t ah[4];
                ldmx4(ah, sb + aoff);
#pragma unroll
                for (int n = 0; n < 4; n++)
                    mma16816(acc[m][n], ah, bh[n]);
            }
        }
    }

    const int g = lane >> 2, t2 = (lane & 3) * 2;
#pragma unroll
    for (int m = 0; m < 4; m++) {
        const size_t grow = (size_t)blockIdx.y * 128 + wm * 64 + m * 16 + g;
#pragma unroll
        for (int n = 0; n < 4; n++) {
            const int col = blockIdx.x * 128 + wn * 32 + n * 8 + t2;
            const float b0 = bias[col], b1 = bias[col + 1];
            uint32_t p01 = pack_bf16(acc[m][n][0] + b0, acc[m][n][1] + b1);
            uint32_t p23 = pack_bf16(acc[m][n][2] + b0, acc[m][n][3] + b1);
            __nv_bfloat16* base = (col < DD) ? (g_q + col) : (g_k + (col - DD));
            *reinterpret_cast<uint32_t*>(base + grow * DD)       = p01;
            *reinterpret_cast<uint32_t*>(base + (grow + 8) * DD) = p23;
        }
    }
}

// ===========================================================================
// logits kernel: CTA = 128(q) x 64(k), K=256, single bf16 HMMA.
// 256 thr / 8 warps in 4m x 2n, warp tile 32x32. __launch_bounds__(256,4):
// 64-reg budget -> 4 CTAs/SM (48% occ). All ldmatrix addresses hoisted.
// 3-stage cp.async. Fused epilogue: exp -> staged coalesced store; z sums.
// ===========================================================================
__global__ __launch_bounds__(256, 4) void logits_kernel() {
    extern __shared__ __align__(16) char tiles[];
    __shared__ float zrow[128];

    const int tid = threadIdx.x;
    const int lane = tid & 31, wid = tid >> 5;
    const int wm = wid & 3, wn = wid >> 2;      // 4 m-groups x 2 n-groups
    const int nt = blockIdx.x, qt = blockIdx.y, b = blockIdx.z;

    if (tid < 128) zrow[tid] = 0.0f;

    const uint32_t sb = smem_u32(tiles);
    const __nv_bfloat16* Qs = g_q + ((size_t)b * SS + (size_t)qt * 128) * DD;
    const __nv_bfloat16* Ks = g_k + ((size_t)b * SS + (size_t)nt * 64) * DD;

    float acc[2][4][4];
#pragma unroll
    for (int m = 0; m < 2; m++)
#pragma unroll
        for (int n = 0; n < 4; n++)
#pragma unroll
            for (int u = 0; u < 4; u++) acc[m][n][u] = 0.0f;

    // hoisted per-thread ldmatrix base addresses (smem absolute, stage 0)
    const uint32_t x4_row = (uint32_t)(lane & 15);
    const uint32_t x4_koff = (uint32_t)((lane >> 4) << 4);
    const uint32_t a_base0 = sb + (uint32_t)(wm * 32 + x4_row) * PADB + x4_koff;
    const uint32_t a_base1 = a_base0 + 16 * PADB;
    const uint32_t b_base0 = sb + LGS_B_OFF + (uint32_t)(wn * 32 + x4_row) * PADB + x4_koff;
    const uint32_t b_base1 = b_base0 + 16 * PADB;

    // hoisted cp.async per-thread coords (3 chunks/thread)
    const int ch_isB[3]  = { tid >= 512 ? 1 : 0, (tid + 256) >= 512 ? 1 : 0, 1 };
    // (chunk = tid, tid+256, tid+512; third is always B)

#define LOAD_STAGE(kt, s)                                                        \
    do {                                                                         \
        _Pragma("unroll")                                                        \
        for (int i = 0; i < 3; i++) {                                            \
            int chunk = tid + i * 256;                                           \
            int isB = ch_isB[i];                                                 \
            int c = chunk - (isB ? 512 : 0);                                     \
            int row = c >> 2, c4 = c & 3;                                        \
            const __nv_bfloat16* src = (isB ? Ks : Qs) + (size_t)row * DD + (kt) * 32 + c4 * 8; \
            cp_async16(sb + (uint32_t)(s) * LGS_STAGE + (isB ? LGS_B_OFF : 0) + row * PADB + c4 * 16, src); \
        }                                                                        \
        asm volatile("cp.async.commit_group;" ::: "memory");                     \
    } while (0)

    LOAD_STAGE(0, 0);
    LOAD_STAGE(1, 1);

    int stage = 0;
    for (int kt = 0; kt < 8; kt++) {
        if (kt < 7) asm volatile("cp.async.wait_group 1;" ::: "memory");
        else        asm volatile("cp.async.wait_group 0;" ::: "memory");
        __syncthreads();
        if (kt + 2 < 8) {
            int ns = stage + 2; if (ns >= 3) ns -= 3;
            LOAD_STAGE(kt + 2, ns);
        }

        const uint32_t soff = (uint32_t)stage * LGS_STAGE;
#pragma unroll
        for (int k16 = 0; k16 < 2; k16++) {
            const uint32_t kb = soff + (uint32_t)(k16 * 32);
            uint32_t br[2][4];
            ldmx4(br[0], b_base0 + kb);
            ldmx4(br[1], b_base1 + kb);
            uint32_t ah[4];
            ldmx4(ah, a_base0 + kb);
#pragma unroll
            for (int nn = 0; nn < 2; nn++) {
                uint32_t b0[2] = { br[nn][0], br[nn][2] };
                uint32_t b1[2] = { br[nn][1], br[nn][3] };
                mma16816(acc[0][nn * 2 + 0], ah, b0);
                mma16816(acc[0][nn * 2 + 1], ah, b1);
            }
            ldmx4(ah, a_base1 + kb);
#pragma unroll
            for (int nn = 0; nn < 2; nn++) {
                uint32_t b0[2] = { br[nn][0], br[nn][2] };
                uint32_t b1[2] = { br[nn][1], br[nn][3] };
                mma16816(acc[1][nn * 2 + 0], ah, b0);
                mma16816(acc[1][nn * 2 + 1], ah, b1);
            }
        }
        if (++stage == 3) stage = 0;
    }
    __syncthreads();   // mainloop reads done; smem becomes P staging

    // ---- epilogue: exp, pack to smem (128 rows x 64 bf16, stride 144) ----
    const int g = lane >> 2, t2 = (lane & 3) * 2;
#pragma unroll
    for (int m = 0; m < 2; m++) {
        const int row_lo = wm * 32 + m * 16 + g;
        float zlo = 0.0f, zhi = 0.0f;
#pragma unroll
        for (int n = 0; n < 4; n++) {
            float e0 = __expf(acc[m][n][0] * 0.0625f);
            float e1 = __expf(acc[m][n][1] * 0.0625f);
            float e2 = __expf(acc[m][n][2] * 0.0625f);
            float e3 = __expf(acc[m][n][3] * 0.0625f);
            zlo += e0 + e1;
            zhi += e2 + e3;
            const int col = wn * 32 + n * 8 + t2;
            *reinterpret_cast<uint32_t*>(tiles + row_lo * EPI_STRIDE + col * 2)       = pack_bf16(e0, e1);
            *reinterpret_cast<uint32_t*>(tiles + (row_lo + 8) * EPI_STRIDE + col * 2) = pack_bf16(e2, e3);
        }
        atomicAdd(&zrow[row_lo], zlo);
        atomicAdd(&zrow[row_lo + 8], zhi);
    }
    __syncthreads();

    // ---- coalesced 16B stores: 128 rows x 128 B = 1024 chunks, 4/thread ----
    const size_t grow0 = (size_t)b * SS + (size_t)qt * 128;
#pragma unroll
    for (int i = 0; i < 4; i++) {
        int chunk = tid + i * 256;
        int row = chunk >> 3, c16 = chunk & 7;
        uint4 v = *reinterpret_cast<const uint4*>(tiles + row * EPI_STRIDE + c16 * 16);
        *reinterpret_cast<uint4*>(g_P + (grow0 + row) * SS + nt * 64 + c16 * 8) = v;
    }
    if (tid < 128)
        atomicAdd(&g_z[grow0 + tid], zrow[tid]);
}

// ===========================================================================
// column weights: w_k += sum_q P[q,k] / z_q.  Column-partitioned (unchanged).
// ===========================================================================
__global__ __launch_bounds__(256) void col_weights_kernel() {
    __shared__ float izs[512];
    __shared__ float ws[16][128];

    const int tid = threadIdx.x;
    const int r0 = blockIdx.x * 512;
    const int c0 = blockIdx.y * 128;
    const int b  = blockIdx.z;

    for (int i = tid; i < 512; i += 256)
        izs[i] = 1.0f / g_z[(size_t)b * SS + r0 + i];
    __syncthreads();

    const int c8 = tid & 15;
    const int rstripe = tid >> 4;

    float acc[8];
#pragma unroll
    for (int j = 0; j < 8; j++) acc[j] = 0.0f;

    const __nv_bfloat16* Pb = g_P + ((size_t)b * SS + r0 + rstripe) * SS + c0 + c8 * 8;
#pragma unroll 4
    for (int i = 0; i < 32; i++) {
        const float iz = izs[rstripe + i * 16];
        uint4 v = *reinterpret_cast<const uint4*>(Pb + (size_t)i * 16 * SS);
        const uint32_t w[4] = {v.x, v.y, v.z, v.w};
#pragma unroll
        for (int h = 0; h < 4; h++) {
            acc[2 * h]     = fmaf(bflo(w[h]), iz, acc[2 * h]);
            acc[2 * h + 1] = fmaf(bfhi(w[h]), iz, acc[2 * h + 1]);
        }
    }

#pragma unroll
    for (int j = 0; j < 8; j++) ws[rstripe][c8 * 8 + j] = acc[j];
    __syncthreads();

    if (tid < 128) {
        float s = 0.0f;
#pragma unroll
        for (int j = 0; j < 16; j++) s += ws[j][tid];
        atomicAdd(&g_w[(size_t)b * SS + c0 + tid], s);
    }
}

// ===========================================================================
// weighted pool: out[b,d] = sum_k w[b,k] * x[b,k,d]
// ===========================================================================
__global__ void out_kernel(const float* __restrict__ x, float* __restrict__ out) {
    const int b = blockIdx.y;
    const int k0 = blockIdx.x * 64;
    const int d = threadIdx.x;

    const float* xp = x + ((size_t)b * SS + k0) * DD + d;
    const float* wp = g_w + (size_t)b * SS + k0;
    float acc = 0.0f;
#pragma unroll 8
    for (int kk = 0; kk < 64; kk++)
        acc = fmaf(wp[kk], xp[(size_t)kk * DD], acc);
    atomicAdd(&out[b * DD + d], acc);
}

// ===========================================================================
extern "C" void kernel_launch(void* const* d_in, const int* in_sizes, int n_in,
                              void* d_out, int out_size) {
    const float* x    = (const float*)d_in[0];
    const float* W    = (const float*)d_in[1];
    const float* bias = (const float*)d_in[2];
    float* out = (float*)d_out;

    cudaFuncSetAttribute(logits_kernel, cudaFuncAttributeMaxDynamicSharedMemorySize, LG_SMEM);

    // 0) zero accumulators                                   (launch #1)
    zero_kernel<<<64, 256>>>(out, out_size);

    // 1) projection                                          (launch #2)
    {
        dim3 grid(D2 / 128, (BB * SS) / 128);
        proj_kernel<<<grid, 256>>>(x, W, bias);
    }

    // probe: shifts logits into the profiled 4th slot        (launch #3)
    probe_kernel<<<1, 32>>>();

    // 2) logits + exp + z  (128x64 CTA, 4 CTAs/SM target)    (launch #4)
    {
        dim3 grid(SS / 64, SS / 128, BB);
        logits_kernel<<<grid, 256, LG_SMEM>>>();
    }

    // 3) column weights                                      (launch #5)
    {
        dim3 grid(SS / 512, SS / 128, BB);
        col_weights_kernel<<<grid, 256>>>();
    }

    // 4) weighted pool                                       (launch #6)
    out_kernel<<<dim3(64, BB), 256>>>(x, out);
}